// round 4
// baseline (speedup 1.0000x reference)
#include <cuda_runtime.h>
#include <stdint.h>

// Hash constants: ((c+1) * PIS[c]) for c = 0..7 (exact 64-bit products).
// tidx = (idx ^ PP[c]) & (TABLE_SIZE-1); valid since idx >= 0, TABLE_SIZE = 2^19.
__constant__ unsigned long long c_pp[8] = {
    774363409ull, 5308871522ull, 2416379583ull, 400000028ull,
    1671816955ull, 8006180478ull, 5140543849ull, 17074907144ull
};

#define TABLE_MASK 0x7FFFFull
#define NRED 32
#define FULLM 0xffffffffu

static __device__ int g_partial[NRED];

// ---------------------------------------------------------------------------
// Kernel 1: per-block max over depth -> g_partial[blockIdx]
// ---------------------------------------------------------------------------
__global__ void depth_reduce_kernel(const int* __restrict__ depth, int n) {
    int m = 0;
    for (int i = blockIdx.x * blockDim.x + threadIdx.x; i < n;
         i += gridDim.x * blockDim.x)
        m = max(m, depth[i]);
    #pragma unroll
    for (int s = 16; s > 0; s >>= 1)
        m = max(m, __shfl_xor_sync(FULLM, m, s));
    __shared__ int sm[32];
    int w = threadIdx.x >> 5;
    if ((threadIdx.x & 31) == 0) sm[w] = m;
    __syncthreads();
    if (threadIdx.x == 0) {
        int nw = (blockDim.x + 31) >> 5;
        int mm = sm[0];
        for (int i = 1; i < nw; i++) mm = max(mm, sm[i]);
        g_partial[blockIdx.x] = mm;
    }
}

// ---------------------------------------------------------------------------
// Kernel 2: main encoding. Block = one ray (256 threads). Warp w = level l.
// inp coords and node box distributed via coalesced LDG + warp shuffles
// (removes ~96 L1tex wavefronts per ray vs scalar loads). Features staged
// through smem (512B/level), each lane emits two float4 output slices so
// warp stores are two fully contiguous 512B STG.128 streams.
// ---------------------------------------------------------------------------
__global__ void __launch_bounds__(256, 6) nbvh_main_kernel(
    const float* __restrict__ inp,          // [R,16,3]
    const int*   __restrict__ history,      // [R,64]
    const float* __restrict__ nodes_min,    // [N,3]
    const float* __restrict__ nodes_extent, // [N,3]
    const float* __restrict__ emb,          // [524288,16]
    float* __restrict__ out)                // [R, 8*16*16]
{
    __shared__ float4 sfeat[8][32];   // [warp][corner*4 + dim_group]
    __shared__ int s_activeL;

    const int tid  = threadIdx.x;
    const int w    = tid >> 5;       // level l
    const int lane = tid & 31;
    const int r    = blockIdx.x;

    if (tid == 0) {
        int m = 0;
        #pragma unroll
        for (int i = 0; i < NRED; i++) m = max(m, g_partial[i]);
        s_activeL = (m < 8) ? m : 8;
    }

    const int idx = history[r * 64 + w];

    // --- feature gather: lane -> (corner = lane>>2, float4 sub = lane&3) ---
    {
        const int c   = lane >> 2;
        const int sub = lane & 3;
        unsigned tix =
            (unsigned)(((unsigned long long)(unsigned)idx ^ c_pp[c]) & TABLE_MASK);
        sfeat[w][lane] =
            reinterpret_cast<const float4*>(emb)[(size_t)tix * 4 + sub];
    }

    // --- inp coords: 2 coalesced 128B LDG, distributed via shuffle ---
    const float* ib = inp + (size_t)r * 48;
    const float va  = ib[lane];        // indices 0..31
    const float vb  = ib[16 + lane];   // indices 16..47

    // --- node box: 1 predicated LDG (lanes 0-5), reciprocal pre-shuffle ---
    float nv = 0.0f;
    if (lane < 6) {
        const float* np_ = (lane < 3) ? nodes_min : nodes_extent;
        nv = np_[(size_t)idx * 3 + (lane < 3 ? lane : lane - 3)];
        if (lane >= 3) nv = __fdividef(1.0f, nv);
    }
    const float pmx = __shfl_sync(FULLM, nv, 0);
    const float pmy = __shfl_sync(FULLM, nv, 1);
    const float pmz = __shfl_sync(FULLM, nv, 2);
    const float rex = __shfl_sync(FULLM, nv, 3);
    const float rey = __shfl_sync(FULLM, nv, 4);
    const float rez = __shfl_sync(FULLM, nv, 5);

    const int p_lo = lane >> 2;            // points p_lo and p_lo+8
    const int dsub = lane & 3;             // float4 dim group
    const int blo  = p_lo * 3;             // 0..21  -> from va
    const int bhi  = (p_lo + 8) * 3 - 16;  // 8..29  -> from vb
    const float xl = __shfl_sync(FULLM, va, blo);
    const float yl = __shfl_sync(FULLM, va, blo + 1);
    const float zl = __shfl_sync(FULLM, va, blo + 2);
    const float xh = __shfl_sync(FULLM, vb, bhi);
    const float yh = __shfl_sync(FULLM, vb, bhi + 1);
    const float zh = __shfl_sync(FULLM, vb, bhi + 2);

    __syncthreads();   // sfeat + s_activeL visible

    const float act = (w < s_activeL) ? 1.0f : 0.0f;

    float wlo[8], whi[8];
    #pragma unroll
    for (int half = 0; half < 2; half++) {
        float x = fminf(fmaxf(((half ? xh : xl) - pmx) * rex, 0.0f), 1.0f);
        float y = fminf(fmaxf(((half ? yh : yl) - pmy) * rey, 0.0f), 1.0f);
        float z = fminf(fmaxf(((half ? zh : zl) - pmz) * rez, 0.0f), 1.0f);
        const float ix = 1.0f - x, iy = 1.0f - y;
        const float z_a = (1.0f - z) * act;   // act folded into z terms
        const float za  = z * act;
        const float xy  = x * y,  ixy  = ix * y;
        const float xiy = x * iy, ixiy = ix * iy;
        float* wv = half ? whi : wlo;
        wv[0] = ixiy * z_a;  wv[1] = xiy * z_a;
        wv[2] = ixy  * z_a;  wv[3] = ixiy * za;
        wv[4] = xiy  * za;   wv[5] = ixy  * za;
        wv[6] = xy   * z_a;  wv[7] = xy   * za;
    }

    float4 alo = make_float4(0.f, 0.f, 0.f, 0.f);
    float4 ahi = make_float4(0.f, 0.f, 0.f, 0.f);
    #pragma unroll
    for (int c = 0; c < 8; c++) {
        const float4 f = sfeat[w][c * 4 + dsub];   // 64B-contiguous LDS.128
        alo.x = fmaf(wlo[c], f.x, alo.x);
        alo.y = fmaf(wlo[c], f.y, alo.y);
        alo.z = fmaf(wlo[c], f.z, alo.z);
        alo.w = fmaf(wlo[c], f.w, alo.w);
        ahi.x = fmaf(whi[c], f.x, ahi.x);
        ahi.y = fmaf(whi[c], f.y, ahi.y);
        ahi.z = fmaf(whi[c], f.z, ahi.z);
        ahi.w = fmaf(whi[c], f.w, ahi.w);
    }

    // Output tile for (r, l): 256 floats = 64 float4; two contiguous 512B
    // warp stores.
    float4* o = reinterpret_cast<float4*>(out) + ((size_t)r * 8 + w) * 64;
    o[lane]      = alo;
    o[32 + lane] = ahi;
}

// ---------------------------------------------------------------------------
extern "C" void kernel_launch(void* const* d_in, const int* in_sizes, int n_in,
                              void* d_out, int out_size) {
    const float* inp     = (const float*)d_in[0];
    const int*   history = (const int*)d_in[1];
    const int*   depth   = (const int*)d_in[2];
    const float* nmin    = (const float*)d_in[3];
    const float* next    = (const float*)d_in[4];
    const float* emb     = (const float*)d_in[5];
    float*       out     = (float*)d_out;

    const int R = in_sizes[2];   // number of rays (= depth element count)

    depth_reduce_kernel<<<NRED, 256>>>(depth, R);
    nbvh_main_kernel<<<R, 256>>>(inp, history, nmin, next, emb, out);
}